// round 10
// baseline (speedup 1.0000x reference)
#include <cuda_runtime.h>
#include <cuda_bf16.h>
#include <cstdint>

// ---------------- scratch (device globals; no allocations allowed) ----------
__device__ __nv_bfloat16 g_qkv0[1024 * 3072], g_qkv1[1024 * 3072]; // qkv planes
__device__ __nv_bfloat16 g_x0[1024 * 1024],    g_x1[1024 * 1024];
__device__ __nv_bfloat16 g_wqkv0[3072 * 1024], g_wqkv1[3072 * 1024];
__device__ __nv_bfloat16 g_wp0[1024 * 1024],   g_wp1[1024 * 1024];
__device__ __nv_bfloat16 g_c0[1024 * 1024],    g_c1[1024 * 1024];  // ctx planes

// ---------------- helpers ----------------------------------------------------
__device__ __forceinline__ uint32_t smem_u32(const void* p) {
    uint32_t a;
    asm("{ .reg .u64 t; cvta.to.shared.u64 t, %1; cvt.u32.u64 %0, t; }" : "=r"(a) : "l"(p));
    return a;
}
#define SMEM_SWIZZLE_128B(b) ((b) ^ (((b) >> 3) & 0x70))

__device__ __forceinline__ void cp_async16(uint32_t dst, const void* src) {
    asm volatile("cp.async.cg.shared.global [%0], [%1], 16;" :: "r"(dst), "l"(src) : "memory");
}
__device__ __forceinline__ void ldsm4(uint32_t& r0, uint32_t& r1, uint32_t& r2,
                                      uint32_t& r3, uint32_t addr) {
    asm volatile("ldmatrix.sync.aligned.m8n8.x4.shared.b16 {%0,%1,%2,%3}, [%4];"
                 : "=r"(r0), "=r"(r1), "=r"(r2), "=r"(r3) : "r"(addr));
}
__device__ __forceinline__ void ldsm4t(uint32_t& r0, uint32_t& r1, uint32_t& r2,
                                       uint32_t& r3, uint32_t addr) {
    asm volatile("ldmatrix.sync.aligned.m8n8.x4.trans.shared.b16 {%0,%1,%2,%3}, [%4];"
                 : "=r"(r0), "=r"(r1), "=r"(r2), "=r"(r3) : "r"(addr));
}
__device__ __forceinline__ void mma16816(float* d, const uint32_t* a, const uint32_t* b) {
    asm volatile(
        "mma.sync.aligned.m16n8k16.row.col.f32.bf16.bf16.f32 "
        "{%0,%1,%2,%3}, {%4,%5,%6,%7}, {%8,%9}, {%0,%1,%2,%3};"
        : "+f"(d[0]), "+f"(d[1]), "+f"(d[2]), "+f"(d[3])
        : "r"(a[0]), "r"(a[1]), "r"(a[2]), "r"(a[3]), "r"(b[0]), "r"(b[1]));
}
__device__ __forceinline__ void split_pack(float a, float b, uint32_t& hi, uint32_t& lo) {
    __nv_bfloat162 h, l;
    h.x = __float2bfloat16_rn(a);
    h.y = __float2bfloat16_rn(b);
    l.x = __float2bfloat16_rn(a - __bfloat162float(h.x));
    l.y = __float2bfloat16_rn(b - __bfloat162float(h.y));
    hi = *(uint32_t*)&h;
    lo = *(uint32_t*)&l;
}

// ---------------- merged split fp32 -> (bf16 hi, bf16 lo) --------------------
__global__ __launch_bounds__(256) void split_all(
    const float* __restrict__ x, const float* __restrict__ wq,
    const float* __restrict__ wp,
    __nv_bfloat16* __restrict__ x0, __nv_bfloat16* __restrict__ x1,
    __nv_bfloat16* __restrict__ q0, __nv_bfloat16* __restrict__ q1,
    __nv_bfloat16* __restrict__ p0, __nv_bfloat16* __restrict__ p1)
{
    int b = blockIdx.x;
    const float* src;
    __nv_bfloat16 *d0, *d1;
    int base;
    if (b < 1024)      { src = x;  d0 = x0; d1 = x1; base = b; }
    else if (b < 4096) { src = wq; d0 = q0; d1 = q1; base = b - 1024; }
    else               { src = wp; d0 = p0; d1 = p1; base = b - 4096; }
    int i = base * 1024 + threadIdx.x * 4;
    float4 v = *(const float4*)(src + i);
    float vv[4] = {v.x, v.y, v.z, v.w};
    __nv_bfloat16 h0[4], h1[4];
#pragma unroll
    for (int j = 0; j < 4; j++) {
        h0[j] = __float2bfloat16_rn(vv[j]);
        h1[j] = __float2bfloat16_rn(vv[j] - __bfloat162float(h0[j]));
    }
    *(uint2*)(d0 + i) = *(const uint2*)h0;
    *(uint2*)(d1 + i) = *(const uint2*)h1;
}

// ---------------- mma.sync GEMM: C = A@B^T + bias, bf16 split-2 -------------
// BM=64, BN=64, K-chunk 64, TRIPLE-buffered smem (3 x 32KB), 1 sync/chunk,
// 2 CTAs/SM. 8 warps: wm = wid&3 (16-row), wn = wid>>2 (32-col group).
// Buffer: [A0 8K][A1 8K][B0 8K][B1 8K]; 128-byte rows, SW128 swizzle.
#define GEMM_SMEM_BYTES (3 * 32768)

__global__ __launch_bounds__(256, 2) void mma_gemm(
    const __nv_bfloat16* __restrict__ A0, const __nv_bfloat16* __restrict__ A1,
    const __nv_bfloat16* __restrict__ B0, const __nv_bfloat16* __restrict__ B1,
    const float* __restrict__ bias, float* __restrict__ C,
    __nv_bfloat16* __restrict__ P0, __nv_bfloat16* __restrict__ P1, int N, int K)
{
    extern __shared__ char smem[];
    const uint32_t sb = smem_u32(smem);
    const int tid  = threadIdx.x;
    const int lane = tid & 31;
    const int wid  = tid >> 5;
    const int wm   = wid & 3;
    const int wn   = wid >> 2;
    const int bm = blockIdx.y, bn = blockIdx.x;

    const __nv_bfloat16* planes[4];
    planes[0] = A0 + (size_t)bm * 64 * K;
    planes[1] = A1 + (size_t)bm * 64 * K;
    planes[2] = B0 + (size_t)bn * 64 * K;
    planes[3] = B1 + (size_t)bn * 64 * K;

    float acc[4][4];
#pragma unroll
    for (int i = 0; i < 4; i++)
#pragma unroll
        for (int q = 0; q < 4; q++) acc[i][q] = 0.0f;

    const int NCH = K / 64;

    auto load_chunk = [&](int c) {
        const uint32_t bb = sb + (uint32_t)(c % 3) * 32768;
        const int k0 = c * 64;
        // 2048 cp16: tile(4) x row(64) x seg(8)
#pragma unroll
        for (int i = 0; i < 8; i++) {
            int idx = i * 256 + tid;
            int tile = idx >> 9, w = idx & 511;
            int row = w >> 3, seg = w & 7;
            cp_async16(bb + tile * 8192
                           + SMEM_SWIZZLE_128B((uint32_t)(row * 128 + seg * 16)),
                       planes[tile] + (size_t)row * K + k0 + seg * 8);
        }
        asm volatile("cp.async.commit_group;" ::: "memory");
    };

    const int a_row  = lane & 15;
    const int a_kofs = (lane >> 4) * 8;
    const int b_row  = ((lane >> 4) << 3) + (lane & 7);
    const int b_kofs = lane & 8;

    load_chunk(0);
    load_chunk(1);

    for (int c = 0; c < NCH; c++) {
        if (c + 1 < NCH) {
            asm volatile("cp.async.wait_group 1;" ::: "memory");
        } else {
            asm volatile("cp.async.wait_group 0;" ::: "memory");
        }
        __syncthreads();   // chunk c ready; also: all reads of buf (c+2)%3 (iter c-1) done
        if (c + 2 < NCH) load_chunk(c + 2);

        const uint32_t bb = sb + (uint32_t)(c % 3) * 32768;
#pragma unroll
        for (int ks = 0; ks < 4; ks++) {
            uint32_t bf[2][2][4];
#pragma unroll
            for (int pl = 0; pl < 2; pl++)
#pragma unroll
                for (int ng = 0; ng < 2; ng++) {
                    int row = wn * 32 + ng * 16 + b_row;
                    ldsm4(bf[pl][ng][0], bf[pl][ng][1], bf[pl][ng][2], bf[pl][ng][3],
                          bb + 16384 + pl * 8192 + SMEM_SWIZZLE_128B(
                              (uint32_t)(row * 128 + (ks * 16 + b_kofs) * 2)));
                }
            uint32_t af0[4], af1[4];
            {
                uint32_t boff = SMEM_SWIZZLE_128B(
                    (uint32_t)((wm * 16 + a_row) * 128 + (ks * 16 + a_kofs) * 2));
                ldsm4(af0[0], af0[1], af0[2], af0[3], bb + boff);
                ldsm4(af1[0], af1[1], af1[2], af1[3], bb + 8192 + boff);
            }
#pragma unroll
            for (int ng = 0; ng < 2; ng++)
#pragma unroll
                for (int hf = 0; hf < 2; hf++) {
                    float* d = acc[ng * 2 + hf];
                    mma16816(d, af0, &bf[0][ng][hf * 2]);
                    mma16816(d, af0, &bf[1][ng][hf * 2]);
                    mma16816(d, af1, &bf[0][ng][hf * 2]);
                }
        }
    }

    // epilogue
    const int gr = bm * 64 + wm * 16 + (lane >> 2);
#pragma unroll
    for (int nt = 0; nt < 4; nt++) {
        int gc = bn * 64 + wn * 32 + nt * 8 + (lane & 3) * 2;
        float b0 = bias[gc], b1 = bias[gc + 1];
        float v0 = acc[nt][0] + b0, v1 = acc[nt][1] + b1;
        float v2 = acc[nt][2] + b0, v3 = acc[nt][3] + b1;
        if (C) {
            *(float2*)(C + (size_t)gr * N + gc)       = make_float2(v0, v1);
            *(float2*)(C + (size_t)(gr + 8) * N + gc) = make_float2(v2, v3);
        } else {
            uint32_t hi, lo;
            split_pack(v0, v1, hi, lo);
            *(uint32_t*)(P0 + (size_t)gr * N + gc) = hi;
            *(uint32_t*)(P1 + (size_t)gr * N + gc) = lo;
            split_pack(v2, v3, hi, lo);
            *(uint32_t*)(P0 + (size_t)(gr + 8) * N + gc) = hi;
            *(uint32_t*)(P1 + (size_t)(gr + 8) * N + gc) = lo;
        }
    }
}

// ---------------- tensor-core flash attention (split-2 bf16) -----------------
// Grid (16 q-blocks of 64 rows, 16 heads) = 256 CTAs, 128 threads = 4 warps,
// 2 CTAs/SM. Warp w owns q-rows [qb*64 + w*16, +16).
// smem: Q planes 2x8KB | KV double buffer 2 x 32KB | 125-float LUT
#define ATTN_SMEM_BYTES (16384 + 65536 + 512)

__global__ __launch_bounds__(128, 2) void attn_mma(
    const __nv_bfloat16* __restrict__ qkv0, const __nv_bfloat16* __restrict__ qkv1,
    const float* __restrict__ bias_table,
    __nv_bfloat16* __restrict__ c0, __nv_bfloat16* __restrict__ c1)
{
    extern __shared__ char smem[];
    const uint32_t sb = smem_u32(smem);
    const uint32_t Q0 = sb, Q1 = sb + 8192;
    const uint32_t KV = sb + 16384;
    float* lut = (float*)(smem + 16384 + 65536);

    const int tid  = threadIdx.x;
    const int lane = tid & 31;
    const int warp = tid >> 5;
    const int h    = blockIdx.y;
    const int qb   = blockIdx.x;
    const int q0r  = qb * 64;

    if (tid < 125) {
        int idx = min(63 * tid, 3968);
        lut[tid] = bias_table[idx * 16 + h];
    }

    // ---- async load Q planes (64 rows x 64 dh): 1024 cp16 over 128 threads --
#pragma unroll
    for (int i = 0; i < 8; i++) {
        int idx = i * 128 + tid;
        int pl  = idx >> 9;
        int w   = idx & 511;
        int row = w >> 3;
        int seg = w & 7;
        const __nv_bfloat16* src = (pl ? qkv1 : qkv0)
            + (size_t)(q0r + row) * 3072 + h * 64 + seg * 8;
        cp_async16((pl ? Q1 : Q0) + SMEM_SWIZZLE_128B((uint32_t)(row * 128 + seg * 16)), src);
    }

    auto load_kv = [&](int c) {
        const uint32_t bb = KV + (uint32_t)(c & 1) * 32768;
        const int m0 = c * 64;
#pragma unroll
        for (int i = 0; i < 16; i++) {
            int idx = i * 128 + tid;
            int tile = idx >> 9;            // 0:k0 1:k1 2:v0 3:v1
            int w    = idx & 511;
            int row  = w >> 3;
            int seg  = w & 7;
            const __nv_bfloat16* base = (tile & 1) ? qkv1 : qkv0;
            int off = (tile >> 1) ? 2048 : 1024;
            cp_async16(bb + tile * 8192 + SMEM_SWIZZLE_128B((uint32_t)(row * 128 + seg * 16)),
                       base + (size_t)(m0 + row) * 3072 + off + h * 64 + seg * 8);
        }
        asm volatile("cp.async.commit_group;" ::: "memory");
    };

    load_kv(0);   // group 0 = Q + chunk0

    const int a_row  = lane & 15;
    const int a_kofs = (lane >> 4) * 8;
    const int b_n    = ((lane >> 4) << 3) + (lane & 7);
    const int b_kofs = lane & 8;
    const int v_kv = ((lane >> 3) & 1) * 8 + (lane & 7);
    const int v_dh = (lane >> 4) * 8;

    const int r0g = q0r + warp * 16 + (lane >> 2);
    const int r1g = r0g + 8;
    const int qs0 = (r0g >> 5) + (r0g & 31);
    const int qs1 = (r1g >> 5) + (r1g & 31);

    uint32_t qa[2][4][4];
    float oacc[8][4];
#pragma unroll
    for (int j = 0; j < 8; j++)
#pragma unroll
        for (int q = 0; q < 4; q++) oacc[j][q] = 0.0f;
    float m0r = -1e30f, m1r = -1e30f, l0 = 0.0f, l1 = 0.0f;

    for (int c = 0; c < 16; c++) {
        if (c + 1 < 16) {
            load_kv(c + 1);
            asm volatile("cp.async.wait_group 1;" ::: "memory");
        } else {
            asm volatile("cp.async.wait_group 0;" ::: "memory");
        }
        __syncthreads();

        if (c == 0) {
#pragma unroll
            for (int pl = 0; pl < 2; pl++)
#pragma unroll
                for (int ks = 0; ks < 4; ks++) {
                    uint32_t boff = (uint32_t)((warp * 16 + a_row) * 128
                                               + (ks * 16 + a_kofs) * 2);
                    ldsm4(qa[pl][ks][0], qa[pl][ks][1], qa[pl][ks][2], qa[pl][ks][3],
                          (pl ? Q1 : Q0) + SMEM_SWIZZLE_128B(boff));
                }
        }

        const uint32_t bb = KV + (uint32_t)(c & 1) * 32768;

        float s[8][4];
#pragma unroll
        for (int j = 0; j < 8; j++)
#pragma unroll
            for (int q = 0; q < 4; q++) s[j][q] = 0.0f;

#pragma unroll
        for (int ks = 0; ks < 4; ks++)
#pragma unroll
            for (int ng = 0; ng < 4; ng++) {
                uint32_t boff = SMEM_SWIZZLE_128B(
                    (uint32_t)((ng * 16 + b_n) * 128 + (ks * 16 + b_kofs) * 2));
                uint32_t kb0[4], kb1[4];
                ldsm4(kb0[0], kb0[1], kb0[2], kb0[3], bb + boff);
                ldsm4(kb1[0], kb1[1], kb1[2], kb1[3], bb + 8192 + boff);
#pragma unroll
                for (int hf = 0; hf < 2; hf++) {
                    float* d = s[ng * 2 + hf];
                    mma16816(d, qa[0][ks], &kb0[hf * 2]);
                    mma16816(d, qa[0][ks], &kb1[hf * 2]);
                    mma16816(d, qa[1][ks], &kb0[hf * 2]);
                }
            }

        const int mbase = c * 64;
        float mx0 = -1e30f, mx1 = -1e30f;
#pragma unroll
        for (int j = 0; j < 8; j++) {
            int mc  = mbase + 8 * j + 2 * (lane & 3);
            int ms0 = (mc >> 5) + (mc & 31);
            int ms1 = ((mc + 1) >> 5) + ((mc + 1) & 31);
            s[j][0] = s[j][0] * 0.125f + lut[qs0 - ms0 + 62];
            s[j][1] = s[j][1] * 0.125f + lut[qs0 - ms1 + 62];
            s[j][2] = s[j][2] * 0.125f + lut[qs1 - ms0 + 62];
            s[j][3] = s[j][3] * 0.125f + lut[qs1 - ms1 + 62];
            mx0 = fmaxf(mx0, fmaxf(s[j][0], s[j][1]));
            mx1 = fmaxf(mx1, fmaxf(s[j][2], s[j][3]));
        }
        mx0 = fmaxf(mx0, __shfl_xor_sync(0xffffffffu, mx0, 1));
        mx0 = fmaxf(mx0, __shfl_xor_sync(0xffffffffu, mx0, 2));
        mx1 = fmaxf(mx1, __shfl_xor_sync(0xffffffffu, mx1, 1));
        mx1 = fmaxf(mx1, __shfl_xor_sync(0xffffffffu, mx1, 2));
        float nm0 = fmaxf(m0r, mx0), nm1 = fmaxf(m1r, mx1);
        float cr0 = __expf(m0r - nm0), cr1 = __expf(m1r - nm1);
        float ps0 = 0.0f, ps1 = 0.0f;
#pragma unroll
        for (int j = 0; j < 8; j++) {
            s[j][0] = __expf(s[j][0] - nm0);
            s[j][1] = __expf(s[j][1] - nm0);
            s[j][2] = __expf(s[j][2] - nm1);
            s[j][3] = __expf(s[j][3] - nm1);
            ps0 += s[j][0] + s[j][1];
            ps1 += s[j][2] + s[j][3];
        }
        ps0 += __shfl_xor_sync(0xffffffffu, ps0, 1);
        ps0 += __shfl_xor_sync(0xffffffffu, ps0, 2);
        ps1 += __shfl_xor_sync(0xffffffffu, ps1, 1);
        ps1 += __shfl_xor_sync(0xffffffffu, ps1, 2);
        l0 = l0 * cr0 + ps0;
        l1 = l1 * cr1 + ps1;
        m0r = nm0; m1r = nm1;
#pragma unroll
        for (int j = 0; j < 8; j++) {
            oacc[j][0] *= cr0; oacc[j][1] *= cr0;
            oacc[j][2] *= cr1; oacc[j][3] *= cr1;
        }

        uint32_t p0a[4][4], p1a[4][4];
#pragma unroll
        for (int ks = 0; ks < 4; ks++) {
            int j0 = 2 * ks, j1 = 2 * ks + 1;
            split_pack(s[j0][0], s[j0][1], p0a[ks][0], p1a[ks][0]);
            split_pack(s[j0][2], s[j0][3], p0a[ks][1], p1a[ks][1]);
            split_pack(s[j1][0], s[j1][1], p0a[ks][2], p1a[ks][2]);
            split_pack(s[j1][2], s[j1][3], p0a[ks][3], p1a[ks][3]);
        }

#pragma unroll
        for (int ks = 0; ks < 4; ks++)
#pragma unroll
            for (int dg = 0; dg < 4; dg++) {
                uint32_t boff = SMEM_SWIZZLE_128B(
                    (uint32_t)((ks * 16 + v_kv) * 128 + (dg * 16 + v_dh) * 2));
                uint32_t vb0[4], vb1[4];
                ldsm4t(vb0[0], vb0[1], vb0[2], vb0[3], bb + 16384 + boff);
                ldsm4t(vb1[0], vb1[1], vb1[2], vb1[3], bb + 24576 + boff);
#pragma unroll
                for (int hf = 0; hf < 2; hf++) {
                    float* d = oacc[dg * 2 + hf];
                    mma16816(d, p0a[ks], &vb0[hf * 2]);
                    mma16816(d, p0a[ks], &vb1[hf * 2]);
                    mma16816(d, p1a[ks], &vb0[hf * 2]);
                }
            }
        __syncthreads();
    }

    float inv0 = 1.0f / l0, inv1 = 1.0f / l1;
#pragma unroll
    for (int j = 0; j < 8; j++) {
        int col = h * 64 + 8 * j + 2 * (lane & 3);
        uint32_t hi, lo;
        split_pack(oacc[j][0] * inv0, oacc[j][1] * inv0, hi, lo);
        *(uint32_t*)(c0 + (size_t)r0g * 1024 + col) = hi;
        *(uint32_t*)(c1 + (size_t)r0g * 1024 + col) = lo;
        split_pack(oacc[j][2] * inv1, oacc[j][3] * inv1, hi, lo);
        *(uint32_t*)(c0 + (size_t)r1g * 1024 + col) = hi;
        *(uint32_t*)(c1 + (size_t)r1g * 1024 + col) = lo;
    }
}

// ---------------- launch -----------------------------------------------------
extern "C" void kernel_launch(void* const* d_in, const int* in_sizes, int n_in,
                              void* d_out, int out_size)
{
    const float* x          = (const float*)d_in[0];
    const float* w_qkv      = (const float*)d_in[1];
    const float* b_qkv      = (const float*)d_in[2];
    const float* w_proj     = (const float*)d_in[3];
    const float* b_proj     = (const float*)d_in[4];
    const float* bias_table = (const float*)d_in[5];
    float* out = (float*)d_out;
    (void)in_sizes; (void)n_in; (void)out_size;

    cudaFuncSetAttribute(mma_gemm, cudaFuncAttributeMaxDynamicSharedMemorySize, GEMM_SMEM_BYTES);
    cudaFuncSetAttribute(attn_mma, cudaFuncAttributeMaxDynamicSharedMemorySize, ATTN_SMEM_BYTES);

    __nv_bfloat16 *qkv0, *qkv1, *x0, *x1, *wq0, *wq1, *wp0, *wp1, *c0, *c1;
    cudaGetSymbolAddress((void**)&qkv0, g_qkv0);  cudaGetSymbolAddress((void**)&qkv1, g_qkv1);
    cudaGetSymbolAddress((void**)&x0, g_x0);      cudaGetSymbolAddress((void**)&x1, g_x1);
    cudaGetSymbolAddress((void**)&wq0, g_wqkv0);  cudaGetSymbolAddress((void**)&wq1, g_wqkv1);
    cudaGetSymbolAddress((void**)&wp0, g_wp0);    cudaGetSymbolAddress((void**)&wp1, g_wp1);
    cudaGetSymbolAddress((void**)&c0, g_c0);      cudaGetSymbolAddress((void**)&c1, g_c1);

    // split inputs/weights into bf16 hi/lo planes (single merged launch)
    split_all<<<5120, 256>>>(x, w_qkv, w_proj, x0, x1, wq0, wq1, wp0, wp1);

    // 1) QKV projection -> bf16 planes (grid 48x16 = 768 CTAs, 2/SM)
    mma_gemm<<<dim3(48, 16), 256, GEMM_SMEM_BYTES>>>(
        x0, x1, wq0, wq1, b_qkv, nullptr, qkv0, qkv1, 3072, 1024);

    // 2) tensor-core flash attention (64-row CTAs, 2/SM) -> ctx bf16 planes
    attn_mma<<<dim3(16, 16), 128, ATTN_SMEM_BYTES>>>(qkv0, qkv1, bias_table, c0, c1);

    // 3) output projection -> fp32 out (grid 16x16 = 256 CTAs, 2/SM)
    mma_gemm<<<dim3(16, 16), 256, GEMM_SMEM_BYTES>>>(
        c0, c1, wp0, wp1, b_proj, out, nullptr, nullptr, 1024, 1024);
}

// round 13
// speedup vs baseline: 1.0515x; 1.0515x over previous
#include <cuda_runtime.h>
#include <cuda_bf16.h>
#include <cstdint>

// ---------------- scratch (device globals; no allocations allowed) ----------
__device__ __nv_bfloat16 g_qkv0[1024 * 3072], g_qkv1[1024 * 3072]; // qkv planes
__device__ __nv_bfloat16 g_x0[1024 * 1024],    g_x1[1024 * 1024];
__device__ __nv_bfloat16 g_wqkv0[3072 * 1024], g_wqkv1[3072 * 1024];
__device__ __nv_bfloat16 g_wp0[1024 * 1024],   g_wp1[1024 * 1024];
__device__ __nv_bfloat16 g_c0[1024 * 1024],    g_c1[1024 * 1024];  // ctx planes

// ---------------- helpers ----------------------------------------------------
__device__ __forceinline__ uint32_t smem_u32(const void* p) {
    uint32_t a;
    asm("{ .reg .u64 t; cvta.to.shared.u64 t, %1; cvt.u32.u64 %0, t; }" : "=r"(a) : "l"(p));
    return a;
}
#define SMEM_SWIZZLE_128B(b) ((b) ^ (((b) >> 3) & 0x70))

__device__ __forceinline__ void cp_async16(uint32_t dst, const void* src) {
    asm volatile("cp.async.cg.shared.global [%0], [%1], 16;" :: "r"(dst), "l"(src) : "memory");
}
__device__ __forceinline__ void ldsm4(uint32_t& r0, uint32_t& r1, uint32_t& r2,
                                      uint32_t& r3, uint32_t addr) {
    asm volatile("ldmatrix.sync.aligned.m8n8.x4.shared.b16 {%0,%1,%2,%3}, [%4];"
                 : "=r"(r0), "=r"(r1), "=r"(r2), "=r"(r3) : "r"(addr));
}
__device__ __forceinline__ void ldsm4t(uint32_t& r0, uint32_t& r1, uint32_t& r2,
                                       uint32_t& r3, uint32_t addr) {
    asm volatile("ldmatrix.sync.aligned.m8n8.x4.trans.shared.b16 {%0,%1,%2,%3}, [%4];"
                 : "=r"(r0), "=r"(r1), "=r"(r2), "=r"(r3) : "r"(addr));
}
__device__ __forceinline__ void mma16816(float* d, const uint32_t* a, const uint32_t* b) {
    asm volatile(
        "mma.sync.aligned.m16n8k16.row.col.f32.bf16.bf16.f32 "
        "{%0,%1,%2,%3}, {%4,%5,%6,%7}, {%8,%9}, {%0,%1,%2,%3};"
        : "+f"(d[0]), "+f"(d[1]), "+f"(d[2]), "+f"(d[3])
        : "r"(a[0]), "r"(a[1]), "r"(a[2]), "r"(a[3]), "r"(b[0]), "r"(b[1]));
}
__device__ __forceinline__ void split_pack(float a, float b, uint32_t& hi, uint32_t& lo) {
    __nv_bfloat162 h, l;
    h.x = __float2bfloat16_rn(a);
    h.y = __float2bfloat16_rn(b);
    l.x = __float2bfloat16_rn(a - __bfloat162float(h.x));
    l.y = __float2bfloat16_rn(b - __bfloat162float(h.y));
    hi = *(uint32_t*)&h;
    lo = *(uint32_t*)&l;
}

// ---------------- merged split fp32 -> (bf16 hi, bf16 lo) --------------------
__global__ __launch_bounds__(256) void split_all(
    const float* __restrict__ x, const float* __restrict__ wq,
    const float* __restrict__ wp,
    __nv_bfloat16* __restrict__ x0, __nv_bfloat16* __restrict__ x1,
    __nv_bfloat16* __restrict__ q0, __nv_bfloat16* __restrict__ q1,
    __nv_bfloat16* __restrict__ p0, __nv_bfloat16* __restrict__ p1)
{
    int b = blockIdx.x;
    const float* src;
    __nv_bfloat16 *d0, *d1;
    int base;
    if (b < 1024)      { src = x;  d0 = x0; d1 = x1; base = b; }
    else if (b < 4096) { src = wq; d0 = q0; d1 = q1; base = b - 1024; }
    else               { src = wp; d0 = p0; d1 = p1; base = b - 4096; }
    int i = base * 1024 + threadIdx.x * 4;
    float4 v = *(const float4*)(src + i);
    float vv[4] = {v.x, v.y, v.z, v.w};
    __nv_bfloat16 h0[4], h1[4];
#pragma unroll
    for (int j = 0; j < 4; j++) {
        h0[j] = __float2bfloat16_rn(vv[j]);
        h1[j] = __float2bfloat16_rn(vv[j] - __bfloat162float(h0[j]));
    }
    *(uint2*)(d0 + i) = *(const uint2*)h0;
    *(uint2*)(d1 + i) = *(const uint2*)h1;
}

// ---------------- mma.sync GEMM: C = A@B^T + bias, bf16 split-2 -------------
// BM=64, BN=64, 128 threads = 4 warps, warp tile 32x32 (wm=wid&1, wn=wid>>1).
// K-chunk 64, double-buffered smem (2 x 32KB), 3 CTAs/SM.
// Sync pattern (R9-verified): issue load(c+1), wait_group 1 (pending = the
// just-issued load, so chunk c is complete), sync, mma, trailing sync (WAR).
#define GEMM_SMEM_BYTES (2 * 32768)

__global__ __launch_bounds__(128, 3) void mma_gemm(
    const __nv_bfloat16* __restrict__ A0, const __nv_bfloat16* __restrict__ A1,
    const __nv_bfloat16* __restrict__ B0, const __nv_bfloat16* __restrict__ B1,
    const float* __restrict__ bias, float* __restrict__ C,
    __nv_bfloat16* __restrict__ P0, __nv_bfloat16* __restrict__ P1, int N, int K)
{
    extern __shared__ char smem[];
    const uint32_t sb = smem_u32(smem);
    const int tid  = threadIdx.x;
    const int lane = tid & 31;
    const int wid  = tid >> 5;
    const int wm   = wid & 1;           // 32-row group
    const int wn   = wid >> 1;          // 32-col group
    const int bm = blockIdx.y, bn = blockIdx.x;

    const __nv_bfloat16* planes[4];
    planes[0] = A0 + (size_t)bm * 64 * K;
    planes[1] = A1 + (size_t)bm * 64 * K;
    planes[2] = B0 + (size_t)bn * 64 * K;
    planes[3] = B1 + (size_t)bn * 64 * K;

    float acc[2][4][4];                 // [mt][ng*2+hf][frag]
#pragma unroll
    for (int i = 0; i < 2; i++)
#pragma unroll
        for (int j = 0; j < 4; j++)
#pragma unroll
            for (int q = 0; q < 4; q++) acc[i][j][q] = 0.0f;

    const int NCH = K / 64;

    auto load_chunk = [&](int c) {
        const uint32_t bb = sb + (uint32_t)(c & 1) * 32768;
        const int k0 = c * 64;
        // 2048 cp16: tile(4) x row(64) x seg(8), 128 threads -> 16 iters
#pragma unroll
        for (int i = 0; i < 16; i++) {
            int idx = i * 128 + tid;
            int tile = idx >> 9, w = idx & 511;
            int row = w >> 3, seg = w & 7;
            cp_async16(bb + tile * 8192
                           + SMEM_SWIZZLE_128B((uint32_t)(row * 128 + seg * 16)),
                       planes[tile] + (size_t)row * K + k0 + seg * 8);
        }
        asm volatile("cp.async.commit_group;" ::: "memory");
    };

    const int a_row  = lane & 15;
    const int a_kofs = (lane >> 4) * 8;
    const int b_row  = ((lane >> 4) << 3) + (lane & 7);
    const int b_kofs = lane & 8;

    load_chunk(0);

    for (int c = 0; c < NCH; c++) {
        if (c + 1 < NCH) {
            load_chunk(c + 1);                              // safe: trailing sync of
            asm volatile("cp.async.wait_group 1;" ::: "memory");  // iter c-1 guards buf
        } else {
            asm volatile("cp.async.wait_group 0;" ::: "memory");
        }
        __syncthreads();   // chunk c visible to all warps

        const uint32_t bb = sb + (uint32_t)(c & 1) * 32768;
#pragma unroll
        for (int ks = 0; ks < 4; ks++) {
            // A frags: [pl][mt]
            uint32_t af[2][2][4];
#pragma unroll
            for (int pl = 0; pl < 2; pl++)
#pragma unroll
                for (int mt = 0; mt < 2; mt++) {
                    int row = wm * 32 + mt * 16 + a_row;
                    ldsm4(af[pl][mt][0], af[pl][mt][1], af[pl][mt][2], af[pl][mt][3],
                          bb + pl * 8192 + SMEM_SWIZZLE_128B(
                              (uint32_t)(row * 128 + (ks * 16 + a_kofs) * 2)));
                }
            // B frags: [pl][ng]
            uint32_t bf[2][2][4];
#pragma unroll
            for (int pl = 0; pl < 2; pl++)
#pragma unroll
                for (int ng = 0; ng < 2; ng++) {
                    int row = wn * 32 + ng * 16 + b_row;
                    ldsm4(bf[pl][ng][0], bf[pl][ng][1], bf[pl][ng][2], bf[pl][ng][3],
                          bb + 16384 + pl * 8192 + SMEM_SWIZZLE_128B(
                              (uint32_t)(row * 128 + (ks * 16 + b_kofs) * 2)));
                }
#pragma unroll
            for (int mt = 0; mt < 2; mt++)
#pragma unroll
                for (int ng = 0; ng < 2; ng++)
#pragma unroll
                    for (int hf = 0; hf < 2; hf++) {
                        float* d = acc[mt][ng * 2 + hf];
                        mma16816(d, af[0][mt], &bf[0][ng][hf * 2]);
                        mma16816(d, af[0][mt], &bf[1][ng][hf * 2]);
                        mma16816(d, af[1][mt], &bf[0][ng][hf * 2]);
                    }
        }
        __syncthreads();   // all reads of buf c&1 done before iter c+1 overwrites it
    }

    // epilogue
#pragma unroll
    for (int mt = 0; mt < 2; mt++) {
        int gr = bm * 64 + wm * 32 + mt * 16 + (lane >> 2);
#pragma unroll
        for (int nt = 0; nt < 4; nt++) {
            int gc = bn * 64 + wn * 32 + nt * 8 + (lane & 3) * 2;
            float b0 = bias[gc], b1 = bias[gc + 1];
            float v0 = acc[mt][nt][0] + b0, v1 = acc[mt][nt][1] + b1;
            float v2 = acc[mt][nt][2] + b0, v3 = acc[mt][nt][3] + b1;
            if (C) {
                *(float2*)(C + (size_t)gr * N + gc)       = make_float2(v0, v1);
                *(float2*)(C + (size_t)(gr + 8) * N + gc) = make_float2(v2, v3);
            } else {
                uint32_t hi, lo;
                split_pack(v0, v1, hi, lo);
                *(uint32_t*)(P0 + (size_t)gr * N + gc) = hi;
                *(uint32_t*)(P1 + (size_t)gr * N + gc) = lo;
                split_pack(v2, v3, hi, lo);
                *(uint32_t*)(P0 + (size_t)(gr + 8) * N + gc) = hi;
                *(uint32_t*)(P1 + (size_t)(gr + 8) * N + gc) = lo;
            }
        }
    }
}

// ---------------- tensor-core flash attention (split-2 bf16, R9 version) ----
// Grid (8 q-blocks of 128 rows, 16 heads), 256 threads = 8 warps.
#define ATTN_SMEM_BYTES (32768 + 65536 + 512)

__global__ __launch_bounds__(256, 1) void attn_mma(
    const __nv_bfloat16* __restrict__ qkv0, const __nv_bfloat16* __restrict__ qkv1,
    const float* __restrict__ bias_table,
    __nv_bfloat16* __restrict__ c0, __nv_bfloat16* __restrict__ c1)
{
    extern __shared__ char smem[];
    const uint32_t sb = smem_u32(smem);
    const uint32_t Q0 = sb, Q1 = sb + 16384;
    const uint32_t KV = sb + 32768;
    float* lut = (float*)(smem + 98304);

    const int tid  = threadIdx.x;
    const int lane = tid & 31;
    const int warp = tid >> 5;
    const int h    = blockIdx.y;
    const int qb   = blockIdx.x;
    const int q0r  = qb * 128;

    if (tid < 125) {
        int idx = min(63 * tid, 3968);
        lut[tid] = bias_table[idx * 16 + h];
    }

#pragma unroll
    for (int i = 0; i < 8; i++) {
        int idx = i * 256 + tid;
        int pl  = idx >> 10;
        int w   = idx & 1023;
        int row = w >> 3;
        int seg = w & 7;
        const __nv_bfloat16* src = (pl ? qkv1 : qkv0)
            + (size_t)(q0r + row) * 3072 + h * 64 + seg * 8;
        cp_async16((pl ? Q1 : Q0) + SMEM_SWIZZLE_128B((uint32_t)(row * 128 + seg * 16)), src);
    }

    auto load_kv = [&](int c) {
        const uint32_t bb = KV + (uint32_t)(c & 1) * 32768;
        const int m0 = c * 64;
#pragma unroll
        for (int i = 0; i < 8; i++) {
            int idx = i * 256 + tid;
            int tile = idx >> 9;
            int w    = idx & 511;
            int row  = w >> 3;
            int seg  = w & 7;
            const __nv_bfloat16* base = (tile & 1) ? qkv1 : qkv0;
            int off = (tile >> 1) ? 2048 : 1024;
            cp_async16(bb + tile * 8192 + SMEM_SWIZZLE_128B((uint32_t)(row * 128 + seg * 16)),
                       base + (size_t)(m0 + row) * 3072 + off + h * 64 + seg * 8);
        }
        asm volatile("cp.async.commit_group;" ::: "memory");
    };

    load_kv(0);

    const int a_row  = lane & 15;
    const int a_kofs = (lane >> 4) * 8;
    const int b_n    = ((lane >> 4) << 3) + (lane & 7);
    const int b_kofs = lane & 8;
    const int v_kv = ((lane >> 3) & 1) * 8 + (lane & 7);
    const int v_dh = (lane >> 4) * 8;

    const int r0g = q0r + warp * 16 + (lane >> 2);
    const int r1g = r0g + 8;
    const int qs0 = (r0g >> 5) + (r0g & 31);
    const int qs1 = (r1g >> 5) + (r1g & 31);

    uint32_t qa[2][4][4];
    float oacc[8][4];
#pragma unroll
    for (int j = 0; j < 8; j++)
#pragma unroll
        for (int q = 0; q < 4; q++) oacc[j][q] = 0.0f;
    float m0r = -1e30f, m1r = -1e30f, l0 = 0.0f, l1 = 0.0f;

    for (int c = 0; c < 16; c++) {
        if (c + 1 < 16) {
            load_kv(c + 1);
            asm volatile("cp.async.wait_group 1;" ::: "memory");
        } else {
            asm volatile("cp.async.wait_group 0;" ::: "memory");
        }
        __syncthreads();

        if (c == 0) {
#pragma unroll
            for (int pl = 0; pl < 2; pl++)
#pragma unroll
                for (int ks = 0; ks < 4; ks++) {
                    uint32_t boff = (uint32_t)((warp * 16 + a_row) * 128
                                               + (ks * 16 + a_kofs) * 2);
                    ldsm4(qa[pl][ks][0], qa[pl][ks][1], qa[pl][ks][2], qa[pl][ks][3],
                          (pl ? Q1 : Q0) + SMEM_SWIZZLE_128B(boff));
                }
        }

        const uint32_t bb = KV + (uint32_t)(c & 1) * 32768;

        float s[8][4];
#pragma unroll
        for (int j = 0; j < 8; j++)
#pragma unroll
            for (int q = 0; q < 4; q++) s[j][q] = 0.0f;

#pragma unroll
        for (int ks = 0; ks < 4; ks++)
#pragma unroll
            for (int ng = 0; ng < 4; ng++) {
                uint32_t boff = SMEM_SWIZZLE_128B(
                    (uint32_t)((ng * 16 + b_n) * 128 + (ks * 16 + b_kofs) * 2));
                uint32_t kb0[4], kb1[4];
                ldsm4(kb0[0], kb0[1], kb0[2], kb0[3], bb + boff);
                ldsm4(kb1[0], kb1[1], kb1[2], kb1[3], bb + 8192 + boff);
#pragma unroll
                for (int hf = 0; hf < 2; hf++) {
                    float* d = s[ng * 2 + hf];
                    mma16816(d, qa[0][ks], &kb0[hf * 2]);
                    mma16816(d, qa[0][ks], &kb1[hf * 2]);
                    mma16816(d, qa[1][ks], &kb0[hf * 2]);
                }
            }

        const int mbase = c * 64;
        float mx0 = -1e30f, mx1 = -1e30f;
#pragma unroll
        for (int j = 0; j < 8; j++) {
            int mc  = mbase + 8 * j + 2 * (lane & 3);
            int ms0 = (mc >> 5) + (mc & 31);
            int ms1 = ((mc + 1) >> 5) + ((mc + 1) & 31);
            s[j][0] = s[j][0] * 0.125f + lut[qs0 - ms0 + 62];
            s[j][1] = s[j][1] * 0.125f + lut[qs0 - ms1 + 62];
            s[j][2] = s[j][2] * 0.125f + lut[qs1 - ms0 + 62];
            s[j][3] = s[j][3] * 0.125f + lut[qs1 - ms1 + 62];
            mx0 = fmaxf(mx0, fmaxf(s[j][0], s[j][1]));
            mx1 = fmaxf(mx1, fmaxf(s[j][2], s[j][3]));
        }
        mx0 = fmaxf(mx0, __shfl_xor_sync(0xffffffffu, mx0, 1));
        mx0 = fmaxf(mx0, __shfl_xor_sync(0xffffffffu, mx0, 2));
        mx1 = fmaxf(mx1, __shfl_xor_sync(0xffffffffu, mx1, 1));
        mx1 = fmaxf(mx1, __shfl_xor_sync(0xffffffffu, mx1, 2));
        float nm0 = fmaxf(m0r, mx0), nm1 = fmaxf(m1r, mx1);
        float cr0 = __expf(m0r - nm0), cr1 = __expf(m1r - nm1);
        float ps0 = 0.0f, ps1 = 0.0f;
#pragma unroll
        for (int j = 0; j < 8; j++) {
            s[j][0] = __expf(s[j][0] - nm0);
            s[j][1] = __expf(s[j][1] - nm0);
            s[j][2] = __expf(s[j][2] - nm1);
            s[j][3] = __expf(s[j][3] - nm1);
            ps0 += s[j][0] + s[j][1];
            ps1 += s[j][2] + s[j][3];
        }
        ps0 += __shfl_xor_sync(0xffffffffu, ps0, 1);
        ps0 += __shfl_xor_sync(0xffffffffu, ps0, 2);
        ps1 += __shfl_xor_sync(0xffffffffu, ps1, 1);
        ps1 += __shfl_xor_sync(0xffffffffu, ps1, 2);
        l0 = l0 * cr0 + ps0;
        l1 = l1 * cr1 + ps1;
        m0r = nm0; m1r = nm1;
#pragma unroll
        for (int j = 0; j < 8; j++) {
            oacc[j][0] *= cr0; oacc[j][1] *= cr0;
            oacc[j][2] *= cr1; oacc[j][3] *= cr1;
        }

        uint32_t p0a[4][4], p1a[4][4];
#pragma unroll
        for (int ks = 0; ks < 4; ks++) {
            int j0 = 2 * ks, j1 = 2 * ks + 1;
            split_pack(s[j0][0], s[j0][1], p0a[ks][0], p1a[ks][0]);
            split_pack(s[j0][2], s[j0][3], p0a[ks][1], p1a[ks][1]);
            split_pack(s[j1][0], s[j1][1], p0a[ks][2], p1a[ks][2]);
            split_pack(s[j1][2], s[j1][3], p0a[ks][3], p1a[ks][3]);
        }

#pragma unroll
        for (int ks = 0; ks < 4; ks++)
#pragma unroll
            for (int dg = 0; dg < 4; dg++) {
                uint32_t boff = SMEM_SWIZZLE_128B(
                    (uint32_t)((ks * 16 + v_kv) * 128 + (dg * 16 + v_dh) * 2));
                uint32_t vb0[4], vb1[4];
                ldsm4t(vb0[0], vb0[1], vb0[2], vb0[3], bb + 16384 + boff);
                ldsm4t(vb1[0], vb1[1], vb1[2], vb1[3], bb + 24576 + boff);
#pragma unroll
                for (int hf = 0; hf < 2; hf++) {
                    float* d = oacc[dg * 2 + hf];
                    mma16816(d, p0a[ks], &vb0[hf * 2]);
                    mma16816(d, p0a[ks], &vb1[hf * 2]);
                    mma16816(d, p1a[ks], &vb0[hf * 2]);
                }
            }
        __syncthreads();
    }

    float inv0 = 1.0f / l0, inv1 = 1.0f / l1;
#pragma unroll
    for (int j = 0; j < 8; j++) {
        int col = h * 64 + 8 * j + 2 * (lane & 3);
        uint32_t hi, lo;
        split_pack(oacc[j][0] * inv0, oacc[j][1] * inv0, hi, lo);
        *(uint32_t*)(c0 + (size_t)r0g * 1024 + col) = hi;
        *(uint32_t*)(c1 + (size_t)r0g * 1024 + col) = lo;
        split_pack(oacc[j][2] * inv1, oacc[j][3] * inv1, hi, lo);
        *(uint32_t*)(c0 + (size_t)r1g * 1024 + col) = hi;
        *(uint32_t*)(c1 + (size_t)r1g * 1024 + col) = lo;
    }
}

// ---------------- launch -----------------------------------------------------
extern "C" void kernel_launch(void* const* d_in, const int* in_sizes, int n_in,
                              void* d_out, int out_size)
{
    const float* x          = (const float*)d_in[0];
    const float* w_qkv      = (const float*)d_in[1];
    const float* b_qkv      = (const float*)d_in[2];
    const float* w_proj     = (const float*)d_in[3];
    const float* b_proj     = (const float*)d_in[4];
    const float* bias_table = (const float*)d_in[5];
    float* out = (float*)d_out;
    (void)in_sizes; (void)n_in; (void)out_size;

    cudaFuncSetAttribute(mma_gemm, cudaFuncAttributeMaxDynamicSharedMemorySize, GEMM_SMEM_BYTES);
    cudaFuncSetAttribute(attn_mma, cudaFuncAttributeMaxDynamicSharedMemorySize, ATTN_SMEM_BYTES);

    __nv_bfloat16 *qkv0, *qkv1, *x0, *x1, *wq0, *wq1, *wp0, *wp1, *c0, *c1;
    cudaGetSymbolAddress((void**)&qkv0, g_qkv0);  cudaGetSymbolAddress((void**)&qkv1, g_qkv1);
    cudaGetSymbolAddress((void**)&x0, g_x0);      cudaGetSymbolAddress((void**)&x1, g_x1);
    cudaGetSymbolAddress((void**)&wq0, g_wqkv0);  cudaGetSymbolAddress((void**)&wq1, g_wqkv1);
    cudaGetSymbolAddress((void**)&wp0, g_wp0);    cudaGetSymbolAddress((void**)&wp1, g_wp1);
    cudaGetSymbolAddress((void**)&c0, g_c0);      cudaGetSymbolAddress((void**)&c1, g_c1);

    // split inputs/weights into bf16 hi/lo planes (single merged launch)
    split_all<<<5120, 256>>>(x, w_qkv, w_proj, x0, x1, wq0, wq1, wp0, wp1);

    // 1) QKV projection -> bf16 planes (grid 48x16 = 768 CTAs, 3/SM)
    mma_gemm<<<dim3(48, 16), 128, GEMM_SMEM_BYTES>>>(
        x0, x1, wq0, wq1, b_qkv, nullptr, qkv0, qkv1, 3072, 1024);

    // 2) tensor-core flash attention (R9 layout) -> ctx bf16 planes
    attn_mma<<<dim3(8, 16), 256, ATTN_SMEM_BYTES>>>(qkv0, qkv1, bias_table, c0, c1);

    // 3) output projection -> fp32 out (grid 16x16 = 256 CTAs, 3/SM)
    mma_gemm<<<dim3(16, 16), 128, GEMM_SMEM_BYTES>>>(
        c0, c1, wp0, wp1, b_proj, out, nullptr, nullptr, 1024, 1024);
}